// round 2
// baseline (speedup 1.0000x reference)
#include <cuda_runtime.h>
#include <math.h>

// ---------------------------------------------------------------------------
// DepthFormer forward, fp32. S=32768 tokens, dim=192, 4 layers.
// ---------------------------------------------------------------------------

#define S_TOT 32768
#define DIMM 192
#define NPATCH 1024   // spatial tokens per depth slice (hp*wp)
#define FD 32         // depth slices
#define NLAYERS 4

// ------------------------- scratch (device globals) ------------------------
__device__ float g_x [S_TOT * DIMM];
__device__ float g_xn[S_TOT * DIMM];
__device__ float g_qkv[S_TOT * 3 * DIMM];
__device__ float g_ao[S_TOT * DIMM];
__device__ float g_a1[32 * 1024 * 256];
__device__ float g_a3[32 * 256 * 1024];
__device__ float g_a2[32 * 256 * 256];      // also depth scores (1024*32*32)
__device__ float g_ql[32 * 256 * 192];
__device__ float g_kl[32 * 256 * 192];
__device__ float g_Z0[32 * 256 * 256];
__device__ float g_Z1[32 * 256 * 256];
__device__ float g_T1[32 * 256 * 256];
__device__ float g_T2[32 * 256 * 256];
__device__ float g_T3[32 * 256 * 256];
__device__ float g_av[1024 * 32 * 192];
__device__ float g_w2[1024 * 32 * 192];
__device__ float g_h [S_TOT * 8 * DIMM];
__device__ float g_hg[S_TOT * 4 * DIMM];
__device__ float g_smax[2];

// ------------------------- kernels ------------------------------------------

// Big GEMM: C[M,N] = A[M,K] @ B[K,N] (+bias[n]) (+resid[m,n]).
// M % 64 == 0, N % 64 == 0, K % 16 == 0 for all call sites.
__global__ void gemm_big_kernel(const float* __restrict__ A, const float* __restrict__ B,
                                float* __restrict__ C, int M, int N, int K,
                                const float* __restrict__ bias, const float* __restrict__ resid)
{
    __shared__ float As[16][65];
    __shared__ float Bs[16][64];
    int bm = blockIdx.y * 64, bn = blockIdx.x * 64;
    int tx = threadIdx.x, ty = threadIdx.y;
    int tid = ty * 16 + tx;
    float acc[4][4] = {};
    for (int k0 = 0; k0 < K; k0 += 16) {
        #pragma unroll
        for (int i = tid; i < 1024; i += 256) {
            int m = i >> 4, k = i & 15;
            As[k][m] = A[(long)(bm + m) * K + k0 + k];
        }
        #pragma unroll
        for (int i = tid; i < 1024; i += 256) {
            int k = i >> 6, n = i & 63;
            Bs[k][n] = B[(long)(k0 + k) * N + bn + n];
        }
        __syncthreads();
        #pragma unroll
        for (int k = 0; k < 16; k++) {
            float a[4], b[4];
            #pragma unroll
            for (int u = 0; u < 4; u++) a[u] = As[k][ty + 16 * u];
            #pragma unroll
            for (int u = 0; u < 4; u++) b[u] = Bs[k][tx + 16 * u];
            #pragma unroll
            for (int u = 0; u < 4; u++)
                #pragma unroll
                for (int v = 0; v < 4; v++)
                    acc[u][v] += a[u] * b[v];
        }
        __syncthreads();
    }
    #pragma unroll
    for (int u = 0; u < 4; u++) {
        int m = bm + ty + 16 * u;
        #pragma unroll
        for (int v = 0; v < 4; v++) {
            int n = bn + tx + 16 * v;
            float val = acc[u][v];
            if (bias)  val += bias[n];
            if (resid) val += resid[(long)m * N + n];
            C[(long)m * N + n] = val;
        }
    }
}

// Batched strided GEMM. C = c0*(A@B) + c1*A.  All of M,N,K % 32 == 0.
// A[b,i,k] = A + b*sAb + i*sAr + k
// transB=0: B[b,k,j] = B + b*sBb + k*sBr + j ; transB=1: B[b,j,k] = B + b*sBb + j*sBr + k
// C[b,i,j] = C + b*sCb + i*sCr + j
__global__ void gemm_bat_kernel(const float* __restrict__ A, const float* __restrict__ B,
                                float* __restrict__ C, int M, int N, int K,
                                long sAb, long sAr, long sBb, long sBr, long sCb, long sCr,
                                int transB, float c0, float c1)
{
    __shared__ float As[32][33];
    __shared__ float Bs[32][33];
    int b = blockIdx.z;
    int bm = blockIdx.y * 32, bn = blockIdx.x * 32;
    const float* Ab = A + (long)b * sAb;
    const float* Bb = B + (long)b * sBb;
    int tx = threadIdx.x, ty = threadIdx.y;
    int tid = ty * 16 + tx;
    float acc[2][2] = {};
    for (int k0 = 0; k0 < K; k0 += 32) {
        #pragma unroll
        for (int i = tid; i < 1024; i += 256) {
            int r = i >> 5, c = i & 31;
            As[r][c] = Ab[(long)(bm + r) * sAr + k0 + c];
        }
        if (!transB) {
            #pragma unroll
            for (int i = tid; i < 1024; i += 256) {
                int kk = i >> 5, n = i & 31;
                Bs[kk][n] = Bb[(long)(k0 + kk) * sBr + bn + n];
            }
        } else {
            #pragma unroll
            for (int i = tid; i < 1024; i += 256) {
                int j = i >> 5, kk = i & 31;
                Bs[kk][j] = Bb[(long)(bn + j) * sBr + k0 + kk];
            }
        }
        __syncthreads();
        #pragma unroll
        for (int k = 0; k < 32; k++) {
            float a0 = As[ty][k], a1 = As[ty + 16][k];
            float b0 = Bs[k][tx], b1 = Bs[k][tx + 16];
            acc[0][0] += a0 * b0; acc[0][1] += a0 * b1;
            acc[1][0] += a1 * b0; acc[1][1] += a1 * b1;
        }
        __syncthreads();
    }
    #pragma unroll
    for (int u = 0; u < 2; u++) {
        int i = bm + ty + 16 * u;
        #pragma unroll
        for (int v = 0; v < 2; v++) {
            int j = bn + tx + 16 * v;
            float val = c0 * acc[u][v];
            if (c1 != 0.0f) val += c1 * Ab[(long)i * sAr + j];
            C[(long)b * sCb + (long)i * sCr + j] = val;
        }
    }
}

// per-row L2 scale-norm over dim=192, one warp per row
__global__ void scale_norm_kernel(const float* __restrict__ x, float* __restrict__ y,
                                  const float* __restrict__ g, int gidx, int rows)
{
    int row = blockIdx.x * 8 + (threadIdx.x >> 5);
    if (row >= rows) return;
    int lane = threadIdx.x & 31;
    const float* xr = x + (long)row * DIMM;
    float v[6]; float ss = 0.f;
    #pragma unroll
    for (int t = 0; t < 6; t++) { v[t] = xr[lane + 32 * t]; ss += v[t] * v[t]; }
    #pragma unroll
    for (int o = 16; o > 0; o >>= 1) ss += __shfl_xor_sync(0xffffffffu, ss, o);
    float nrm = fmaxf(sqrtf(ss), 1e-5f);
    float s = g[gidx] / nrm;
    float* yr = y + (long)row * DIMM;
    #pragma unroll
    for (int t = 0; t < 6; t++) yr[lane + 32 * t] = v[t] * s;
}

// in-place row softmax, one warp per row
__global__ void softmax_kernel(float* __restrict__ Sm, long rows, int n)
{
    long row = (long)blockIdx.x * 8 + (threadIdx.x >> 5);
    if (row >= rows) return;
    int lane = threadIdx.x & 31;
    float* p = Sm + row * n;
    float mx = -1e30f;
    for (int j = lane; j < n; j += 32) mx = fmaxf(mx, p[j]);
    #pragma unroll
    for (int o = 16; o > 0; o >>= 1) mx = fmaxf(mx, __shfl_xor_sync(0xffffffffu, mx, o));
    float sum = 0.f;
    for (int j = lane; j < n; j += 32) { float e = expf(p[j] - mx); p[j] = e; sum += e; }
    #pragma unroll
    for (int o = 16; o > 0; o >>= 1) sum += __shfl_xor_sync(0xffffffffu, sum, o);
    float inv = 1.f / sum;
    for (int j = lane; j < n; j += 32) p[j] *= inv;
}

// landmark means (spatial, l=4): qL/kL [32,256,192]
__global__ void landmark_kernel(const float* __restrict__ qkv,
                                float* __restrict__ qL, float* __restrict__ kL)
{
    int idx = blockIdx.x * blockDim.x + threadIdx.x;
    if (idx >= 32 * 256 * 192) return;
    int c = idx % 192;
    int j = (idx / 192) & 255;
    int f = idx / (192 * 256);
    long base = ((long)f * 1024 + j * 4) * 576;
    float sq = 0.f, sk = 0.f;
    #pragma unroll
    for (int t = 0; t < 4; t++) {
        sq += qkv[base + (long)t * 576 + c];
        sk += qkv[base + (long)t * 576 + 192 + c];
    }
    qL[idx] = sq * 0.25f;
    kL[idx] = sk * 0.25f;
}

__global__ void zero2_kernel(float* p) { if (threadIdx.x < 2) p[threadIdx.x] = 0.f; }

__global__ void rowabs_max_kernel(const float* __restrict__ Sm, float* smax, long rows, int n)
{
    long row = (long)blockIdx.x * 8 + (threadIdx.x >> 5);
    if (row >= rows) return;
    int lane = threadIdx.x & 31;
    const float* p = Sm + row * n;
    float s = 0.f;
    for (int j = lane; j < n; j += 32) s += fabsf(p[j]);
    #pragma unroll
    for (int o = 16; o > 0; o >>= 1) s += __shfl_xor_sync(0xffffffffu, s, o);
    if (lane == 0) atomicMax((int*)smax, __float_as_int(s));
}

__global__ void colabs_max_kernel(const float* __restrict__ Sm, float* smax, int batch, int n)
{
    int t = blockIdx.x * blockDim.x + threadIdx.x;
    if (t >= batch * n) return;
    int b = t / n, j = t % n;
    const float* p = Sm + (long)b * n * n + j;
    float s = 0.f;
    for (int i = 0; i < n; i++) s += fabsf(p[(long)i * n]);
    atomicMax((int*)(smax + 1), __float_as_int(s));
}

__global__ void transpose_scale_kernel(const float* __restrict__ Sm, float* __restrict__ Z,
                                       const float* smax, int n)
{
    __shared__ float tile[32][33];
    int b = blockIdx.z;
    int x0 = blockIdx.x * 32, y0 = blockIdx.y * 32;
    const float* Sb = Sm + (long)b * n * n;
    tile[threadIdx.y][threadIdx.x] = Sb[(long)(y0 + threadIdx.y) * n + x0 + threadIdx.x];
    __syncthreads();
    float s = 1.0f / (smax[0] * smax[1]);
    Z[(long)b * n * n + (long)(x0 + threadIdx.y) * n + y0 + threadIdx.x] =
        tile[threadIdx.x][threadIdx.y] * s;
}

// GEGLU: hg[m,j] = h[m,j] * gelu_exact(h[m,768+j])
__global__ void geglu_kernel(const float* __restrict__ h, float* __restrict__ hg)
{
    long idx = (long)blockIdx.x * blockDim.x + threadIdx.x;
    if (idx >= (long)S_TOT * 768) return;
    long m = idx / 768; int j = (int)(idx % 768);
    float a  = h[m * 1536 + j];
    float gt = h[m * 1536 + 768 + j];
    float gl = 0.5f * gt * (1.0f + erff(gt * 0.70710678118654752f));
    hg[idx] = a * gl;
}

// patchify: 'b c d (h p1) (w p2) -> b (d h w) (p1 p2 c)' for B=1,C=3,D=32,H=W=256,P=8
__global__ void patchify_kernel(const float* __restrict__ vol, float* __restrict__ vp)
{
    long idx = (long)blockIdx.x * blockDim.x + threadIdx.x;
    if (idx >= (long)S_TOT * DIMM) return;
    int s = (int)(idx / DIMM);
    int k = (int)(idx % DIMM);
    int d = s >> 10;
    int h = (s >> 5) & 31;
    int w = s & 31;
    int p1 = k / 24; int r = k % 24; int p2 = r / 3; int c = r % 3;
    vp[idx] = vol[(((long)c * 32 + d) * 256 + h * 8 + p1) * 256 + w * 8 + p2];
}

// ------------------------- host orchestration --------------------------------

static void big(const float* A, const float* B, float* C, int M, int N, int K,
                const float* bias, const float* resid)
{
    dim3 grid(N / 64, M / 64), block(16, 16);
    gemm_big_kernel<<<grid, block>>>(A, B, C, M, N, K, bias, resid);
}

static void bgemm(const float* A, long sAb, long sAr,
                  const float* B, long sBb, long sBr, int transB,
                  float* C, long sCb, long sCr,
                  int batch, int M, int N, int K, float c0, float c1)
{
    dim3 grid(N / 32, M / 32, batch), block(16, 16);
    gemm_bat_kernel<<<grid, block>>>(A, B, C, M, N, K, sAb, sAr, sBb, sBr, sCb, sCr,
                                     transB, c0, c1);
}

static void softmax_rows(float* p, long rows, int n)
{
    int blocks = (int)((rows + 7) / 8);
    softmax_kernel<<<blocks, 256>>>(p, rows, n);
}

// Newton-Schulz pseudo-inverse of batched square matrices S[batch,n,n]
static float* run_pinv(const float* Sm, int batch, int n,
                       float* Z0, float* Z1, float* T1, float* T2, float* T3, float* smax)
{
    zero2_kernel<<<1, 32>>>(smax);
    long rows = (long)batch * n;
    rowabs_max_kernel<<<(int)((rows + 7) / 8), 256>>>(Sm, smax, rows, n);
    colabs_max_kernel<<<(batch * n + 255) / 256, 256>>>(Sm, smax, batch, n);
    dim3 tg(n / 32, n / 32, batch);
    transpose_scale_kernel<<<tg, dim3(32, 32)>>>(Sm, Z0, smax, n);
    long nn = (long)n * n;
    float* Zc = Z0; float* Zn = Z1;
    for (int it = 0; it < 6; it++) {
        // xz = S @ Z
        bgemm(Sm, nn, n, Zc, nn, n, 0, T1, nn, n, batch, n, n, n, 1.f, 0.f);
        // u = 7*xz - xz@xz
        bgemm(T1, nn, n, T1, nn, n, 0, T2, nn, n, batch, n, n, n, -1.f, 7.f);
        // t = 15*xz - xz@u
        bgemm(T1, nn, n, T2, nn, n, 0, T3, nn, n, batch, n, n, n, -1.f, 15.f);
        // Znew = 3.25*Z - 0.25*Z@t
        bgemm(Zc, nn, n, T3, nn, n, 0, Zn, nn, n, batch, n, n, n, -0.25f, 3.25f);
        float* t = Zc; Zc = Zn; Zn = t;
    }
    return Zc;
}

#define GETSYM(var, sym) do { void* _p; cudaGetSymbolAddress(&_p, sym); var = (float*)_p; } while (0)

extern "C" void kernel_launch(void* const* d_in, const int* in_sizes, int n_in,
                              void* d_out, int out_size)
{
    (void)in_sizes; (void)n_in; (void)out_size;
    const float* volume      = (const float*)d_in[0];
    const float* patch_w     = (const float*)d_in[1];
    const float* patch_b     = (const float*)d_in[2];
    const float* pos_emb     = (const float*)d_in[3];
    const float* gd          = (const float*)d_in[4];
    const float* qkv_depth   = (const float*)d_in[5];
    const float* outw_depth  = (const float*)d_in[6];
    const float* outb_depth  = (const float*)d_in[7];
    const float* gs          = (const float*)d_in[8];
    const float* qkv_spatial = (const float*)d_in[9];
    const float* outw_spatial= (const float*)d_in[10];
    const float* outb_spatial= (const float*)d_in[11];
    const float* gf          = (const float*)d_in[12];
    const float* ff_w1       = (const float*)d_in[13];
    const float* ff_b1       = (const float*)d_in[14];
    const float* ff_w2       = (const float*)d_in[15];
    const float* ff_b2       = (const float*)d_in[16];
    const float* g_final     = (const float*)d_in[17];

    float *X, *XN, *QKV, *AO, *A1, *A2, *A3, *QL, *KL, *Z0, *Z1, *T1, *T2, *T3, *AV, *W2, *H, *HG, *SMAX;
    GETSYM(X, g_x);   GETSYM(XN, g_xn); GETSYM(QKV, g_qkv); GETSYM(AO, g_ao);
    GETSYM(A1, g_a1); GETSYM(A2, g_a2); GETSYM(A3, g_a3);
    GETSYM(QL, g_ql); GETSYM(KL, g_kl);
    GETSYM(Z0, g_Z0); GETSYM(Z1, g_Z1); GETSYM(T1, g_T1); GETSYM(T2, g_T2); GETSYM(T3, g_T3);
    GETSYM(AV, g_av); GETSYM(W2, g_w2); GETSYM(H, g_h);   GETSYM(HG, g_hg);
    GETSYM(SMAX, g_smax);

    const float SCALE = 0.0721687836487032f; // 192^-0.5

    // ---- patch embed: x = patchify(vol) @ patch_w + patch_b + pos_emb
    {
        long tot = (long)S_TOT * DIMM;
        patchify_kernel<<<(int)((tot + 255) / 256), 256>>>(volume, XN);
        big(XN, patch_w, X, S_TOT, DIMM, DIMM, patch_b, pos_emb);
    }

    for (int i = 0; i < NLAYERS; i++) {
        const float* Wqkv_d = qkv_depth   + (long)i * DIMM * 3 * DIMM;
        const float* Wout_d = outw_depth  + (long)i * DIMM * DIMM;
        const float* bout_d = outb_depth  + (long)i * DIMM;
        const float* Wqkv_s = qkv_spatial + (long)i * DIMM * 3 * DIMM;
        const float* Wout_s = outw_spatial+ (long)i * DIMM * DIMM;
        const float* bout_s = outb_spatial+ (long)i * DIMM;
        const float* W1     = ff_w1 + (long)i * DIMM * 8 * DIMM;
        const float* B1     = ff_b1 + (long)i * 8 * DIMM;
        const float* W2w    = ff_w2 + (long)i * 4 * DIMM * DIMM;
        const float* B2     = ff_b2 + (long)i * DIMM;

        // ================= depth attention (batch=1024 over n, seq=32) ======
        scale_norm_kernel<<<S_TOT / 8, 256>>>(X, XN, gd, i, S_TOT);
        big(XN, Wqkv_d, QKV, S_TOT, 3 * DIMM, DIMM, nullptr, nullptr);
        // scores S[b=1024,32,32] = SCALE * q @ k^T  (landmarks == seq here)
        bgemm(QKV,       576, (long)1024 * 576,
              QKV + 192, 576, (long)1024 * 576, 1,
              A2, 32 * 32, 32,
              1024, 32, 32, DIMM, SCALE, 0.f);
        softmax_rows(A2, (long)1024 * 32, 32);
        float* Zd = run_pinv(A2, 1024, 32, Z0, Z1, T1, T2, T3, SMAX);
        // Av = S @ v
        bgemm(A2, 32 * 32, 32,
              QKV + 384, 576, (long)1024 * 576, 0,
              AV, 32 * 192, 192,
              1024, 32, 192, 32, 1.f, 0.f);
        // w = Z @ Av
        bgemm(Zd, 32 * 32, 32,
              AV, 32 * 192, 192, 0,
              W2, 32 * 192, 192,
              1024, 32, 192, 32, 1.f, 0.f);
        // out = S @ w  (unfold: row = f*1024 + n)
        bgemm(A2, 32 * 32, 32,
              W2, 32 * 192, 192, 0,
              AO, 192, (long)1024 * 192,
              1024, 32, 192, 32, 1.f, 0.f);
        big(AO, Wout_d, X, S_TOT, DIMM, DIMM, bout_d, X);

        // ================= spatial attention (batch=32 over f, seq=1024) ====
        scale_norm_kernel<<<S_TOT / 8, 256>>>(X, XN, gs, i, S_TOT);
        big(XN, Wqkv_s, QKV, S_TOT, 3 * DIMM, DIMM, nullptr, nullptr);
        landmark_kernel<<<(32 * 256 * 192 + 255) / 256, 256>>>(QKV, QL, KL);
        // a1 = softmax(SCALE * q @ kL^T)  [32,1024,256]
        bgemm(QKV, (long)1024 * 576, 576,
              KL, 256 * 192, 192, 1,
              A1, (long)1024 * 256, 256,
              32, 1024, 256, DIMM, SCALE, 0.f);
        // a2 = softmax(SCALE * qL @ kL^T) [32,256,256]
        bgemm(QL, 256 * 192, 192,
              KL, 256 * 192, 192, 1,
              A2, 256 * 256, 256,
              32, 256, 256, DIMM, SCALE, 0.f);
        // a3 = softmax(SCALE * qL @ k^T)  [32,256,1024]
        bgemm(QL, 256 * 192, 192,
              QKV + 192, (long)1024 * 576, 576, 1,
              A3, (long)256 * 1024, 1024,
              32, 256, 1024, DIMM, SCALE, 0.f);
        softmax_rows(A1, (long)32 * 1024, 256);
        softmax_rows(A2, (long)32 * 256, 256);
        softmax_rows(A3, (long)32 * 256, 1024);
        float* Zs = run_pinv(A2, 32, 256, Z0, Z1, T1, T2, T3, SMAX);
        // a3v = a3 @ v  [32,256,192]
        bgemm(A3, (long)256 * 1024, 1024,
              QKV + 384, (long)1024 * 576, 576, 0,
              AV, 256 * 192, 192,
              32, 256, 192, 1024, 1.f, 0.f);
        // w = Z @ a3v
        bgemm(Zs, (long)256 * 256, 256,
              AV, 256 * 192, 192, 0,
              W2, 256 * 192, 192,
              32, 256, 192, 256, 1.f, 0.f);
        // out = a1 @ w (contiguous seq order)
        bgemm(A1, (long)1024 * 256, 256,
              W2, 256 * 192, 192, 0,
              AO, (long)1024 * 192, 192,
              32, 1024, 192, 256, 1.f, 0.f);
        big(AO, Wout_s, X, S_TOT, DIMM, DIMM, bout_s, X);

        // ================= GEGLU feed-forward ================================
        scale_norm_kernel<<<S_TOT / 8, 256>>>(X, XN, gf, i, S_TOT);
        big(XN, W1, H, S_TOT, 8 * DIMM, DIMM, B1, nullptr);
        geglu_kernel<<<(int)(((long)S_TOT * 768 + 255) / 256), 256>>>(H, HG);
        big(HG, W2w, X, S_TOT, DIMM, 4 * DIMM, B2, X);
    }

    // ---- final scale norm -> output
    scale_norm_kernel<<<S_TOT / 8, 256>>>(X, (float*)d_out, g_final, 0, S_TOT);
}

// round 5
// speedup vs baseline: 1.7337x; 1.7337x over previous
#include <cuda_runtime.h>
#include <math.h>

// ---------------------------------------------------------------------------
// DepthFormer forward, fp32. S=32768 tokens, dim=192, 4 layers.
// R5: 256x64 double-buffered GEMM (8x8 micro-tile) + fused depth attention.
// ---------------------------------------------------------------------------

#define S_TOT 32768
#define DIMM 192
#define NLAYERS 4

// ------------------------- scratch (device globals) ------------------------
__device__ float g_x [S_TOT * DIMM];
__device__ float g_xn[S_TOT * DIMM];
__device__ float g_qkv[S_TOT * 3 * DIMM];
__device__ float g_ao[S_TOT * DIMM];
__device__ float g_a1[32 * 1024 * 256];
__device__ float g_a3[32 * 256 * 1024];
__device__ float g_a2[32 * 256 * 256];      // spatial a2; also depth scores (1024*32*32)
__device__ float g_ql[32 * 256 * 192];
__device__ float g_kl[32 * 256 * 192];
__device__ float g_Z0[32 * 256 * 256];
__device__ float g_Z1[32 * 256 * 256];
__device__ float g_T1[32 * 256 * 256];
__device__ float g_T2[32 * 256 * 256];
__device__ float g_T3[32 * 256 * 256];
__device__ float g_av[32 * 256 * 192];
__device__ float g_w2[32 * 256 * 192];
__device__ float g_h [S_TOT * 8 * DIMM];
__device__ float g_hg[S_TOT * 4 * DIMM];
__device__ float g_smax[2];

// ---------------------------------------------------------------------------
// Unified GEMM: C[b,m,n] = c0 * A[b]@B[b] (+bias[n]) (+c1*resid[b,m,n])
// Tile 256x64x16, 256 threads, 8x8 micro-tile, double-buffered smem,
// register prefetch, one __syncthreads per K-step.
// Requires M%256==0, N%64==0, K%16==0, row strides %4, 16B-aligned bases.
// ---------------------------------------------------------------------------
#define APAD 260
#define BPAD 68

#define LOAD_TILE(k0) do {                                                          \
    _Pragma("unroll")                                                               \
    for (int t = 0; t < 4; t++) {                                                   \
        int idx = tid + t * 256;                                                    \
        pa[t] = *(const float4*)&Ab[(bm + (idx >> 2)) * sAr + (k0) + (idx & 3) * 4];\
    }                                                                               \
    if (!transB)                                                                    \
        pb = *(const float4*)&Bb[(long)((k0) + (tid >> 4)) * sBr + bn + (tid & 15) * 4]; \
    else                                                                            \
        pb = *(const float4*)&Bb[(bn + (tid >> 2)) * sBr + (k0) + (tid & 3) * 4];   \
} while (0)

#define STORE_STAGE(st) do {                                                        \
    _Pragma("unroll")                                                               \
    for (int t = 0; t < 4; t++) {                                                   \
        int idx = tid + t * 256;                                                    \
        int row = idx >> 2, k4 = (idx & 3) * 4;                                     \
        As[st][(k4 + 0) * APAD + row] = pa[t].x;                                    \
        As[st][(k4 + 1) * APAD + row] = pa[t].y;                                    \
        As[st][(k4 + 2) * APAD + row] = pa[t].z;                                    \
        As[st][(k4 + 3) * APAD + row] = pa[t].w;                                    \
    }                                                                               \
    if (!transB) {                                                                  \
        *(float4*)&Bs[st][(tid >> 4) * BPAD + (tid & 15) * 4] = pb;                 \
    } else {                                                                        \
        int n = tid >> 2, k4 = (tid & 3) * 4;                                       \
        Bs[st][(k4 + 0) * BPAD + n] = pb.x;                                         \
        Bs[st][(k4 + 1) * BPAD + n] = pb.y;                                         \
        Bs[st][(k4 + 2) * BPAD + n] = pb.z;                                         \
        Bs[st][(k4 + 3) * BPAD + n] = pb.w;                                         \
    }                                                                               \
} while (0)

__global__ __launch_bounds__(256) void gemm256_kernel(
    const float* __restrict__ A, const float* __restrict__ B, float* __restrict__ C,
    int M, int N, int K,
    long sAb, long sAr, long sBb, long sBr, long sCb, long sCr,
    int transB, float c0,
    const float* __restrict__ bias,
    const float* __restrict__ resid, long sRb, long sRr, float c1)
{
    __shared__ float As[2][16 * APAD];
    __shared__ float Bs[2][16 * BPAD];
    int b = blockIdx.z;
    long bm = (long)blockIdx.y * 256, bn = (long)blockIdx.x * 64;
    const float* Ab = A + (long)b * sAb;
    const float* Bb = B + (long)b * sBb;
    int tid = threadIdx.x;
    int ty = tid >> 3, tx = tid & 7;

    float4 pa[4]; float4 pb;
    float acc[8][8] = {};

    LOAD_TILE(0);
    STORE_STAGE(0);
    __syncthreads();

    int st = 0;
    for (int k0 = 0; k0 < K; k0 += 16) {
        bool more = (k0 + 16) < K;
        if (more) LOAD_TILE(k0 + 16);
        #pragma unroll
        for (int k = 0; k < 16; k++) {
            float4 a0 = *(float4*)&As[st][k * APAD + ty * 8];
            float4 a1 = *(float4*)&As[st][k * APAD + ty * 8 + 4];
            float4 b0 = *(float4*)&Bs[st][k * BPAD + tx * 8];
            float4 b1 = *(float4*)&Bs[st][k * BPAD + tx * 8 + 4];
            float av[8] = {a0.x, a0.y, a0.z, a0.w, a1.x, a1.y, a1.z, a1.w};
            float bv[8] = {b0.x, b0.y, b0.z, b0.w, b1.x, b1.y, b1.z, b1.w};
            #pragma unroll
            for (int u = 0; u < 8; u++)
                #pragma unroll
                for (int v = 0; v < 8; v++)
                    acc[u][v] += av[u] * bv[v];
        }
        if (more) {
            STORE_STAGE(st ^ 1);
            __syncthreads();
            st ^= 1;
        }
    }

    float4 bv0 = make_float4(0.f, 0.f, 0.f, 0.f);
    float4 bv1 = make_float4(0.f, 0.f, 0.f, 0.f);
    if (bias) {
        bv0 = *(const float4*)&bias[bn + tx * 8];
        bv1 = *(const float4*)&bias[bn + tx * 8 + 4];
    }
    #pragma unroll
    for (int u = 0; u < 8; u++) {
        long m = bm + ty * 8 + u;
        float4 o0, o1;
        o0.x = c0 * acc[u][0] + bv0.x; o0.y = c0 * acc[u][1] + bv0.y;
        o0.z = c0 * acc[u][2] + bv0.z; o0.w = c0 * acc[u][3] + bv0.w;
        o1.x = c0 * acc[u][4] + bv1.x; o1.y = c0 * acc[u][5] + bv1.y;
        o1.z = c0 * acc[u][6] + bv1.z; o1.w = c0 * acc[u][7] + bv1.w;
        if (resid) {
            const float* rp = &resid[(long)b * sRb + m * sRr + bn + tx * 8];
            float4 r0 = *(const float4*)rp;
            float4 r1 = *(const float4*)(rp + 4);
            o0.x += c1 * r0.x; o0.y += c1 * r0.y; o0.z += c1 * r0.z; o0.w += c1 * r0.w;
            o1.x += c1 * r1.x; o1.y += c1 * r1.y; o1.z += c1 * r1.z; o1.w += c1 * r1.w;
        }
        float* cp = &C[(long)b * sCb + m * sCr + bn + tx * 8];
        *(float4*)cp = o0;
        *(float4*)(cp + 4) = o1;
    }
}

// ---------------------------------------------------------------------------
// Depth attention fused kernels. batch b = spatial patch index (0..1023),
// sequence = 32 depth slices. qkv row for (f, b) at QKV[(f*1024+b)*576].
// ---------------------------------------------------------------------------

// D1: S = softmax(SCALE * q @ k^T) per batch -> A2[b*1024 + i*32 + j]
__global__ __launch_bounds__(256) void depth_scores_kernel(
    const float* __restrict__ qkv, float* __restrict__ Sout)
{
    extern __shared__ float sm[];
    float* qb = sm;            // [32][192]
    float* kT = sm + 6144;     // [192][36]
    int b = blockIdx.x, tid = threadIdx.x;
    for (int t = 0; t < 6; t++) {
        int idx = tid + t * 256;          // 0..1535 float4s
        int f = idx / 48, c4 = (idx % 48) * 4;
        long base = ((long)f * 1024 + b) * 576 + c4;
        float4 qv = *(const float4*)&qkv[base];
        float4 kv = *(const float4*)&qkv[base + 192];
        *(float4*)&qb[f * 192 + c4] = qv;
        kT[(c4 + 0) * 36 + f] = kv.x; kT[(c4 + 1) * 36 + f] = kv.y;
        kT[(c4 + 2) * 36 + f] = kv.z; kT[(c4 + 3) * 36 + f] = kv.w;
    }
    __syncthreads();
    int i = tid >> 3, jq = (tid & 7) * 4;
    float4 acc = make_float4(0.f, 0.f, 0.f, 0.f);
    for (int c = 0; c < 192; c++) {
        float qv = qb[i * 192 + c];
        float4 kv = *(float4*)&kT[c * 36 + jq];
        acc.x += qv * kv.x; acc.y += qv * kv.y; acc.z += qv * kv.z; acc.w += qv * kv.w;
    }
    const float SCALE = 0.0721687836487032f;
    acc.x *= SCALE; acc.y *= SCALE; acc.z *= SCALE; acc.w *= SCALE;
    float mx = fmaxf(fmaxf(acc.x, acc.y), fmaxf(acc.z, acc.w));
    #pragma unroll
    for (int o = 4; o > 0; o >>= 1) mx = fmaxf(mx, __shfl_xor_sync(0xffffffffu, mx, o));
    acc.x = expf(acc.x - mx); acc.y = expf(acc.y - mx);
    acc.z = expf(acc.z - mx); acc.w = expf(acc.w - mx);
    float sum = acc.x + acc.y + acc.z + acc.w;
    #pragma unroll
    for (int o = 4; o > 0; o >>= 1) sum += __shfl_xor_sync(0xffffffffu, sum, o);
    float inv = 1.f / sum;
    acc.x *= inv; acc.y *= inv; acc.z *= inv; acc.w *= inv;
    *(float4*)&Sout[(long)b * 1024 + i * 32 + jq] = acc;
}

// 32x32 smem matmul helper: C = c0*A@B + c1*R  (all [32][36] smem, 256 thr)
__device__ __forceinline__ void mm32(const float* __restrict__ A, const float* __restrict__ B,
                                     float* __restrict__ C, const float* __restrict__ R,
                                     float c0, float c1, int tid)
{
    int i = tid >> 3, jq = (tid & 7) * 4;
    float4 acc = make_float4(0.f, 0.f, 0.f, 0.f);
    #pragma unroll 8
    for (int k = 0; k < 32; k++) {
        float a = A[i * 36 + k];
        float4 bv = *(const float4*)&B[k * 36 + jq];
        acc.x += a * bv.x; acc.y += a * bv.y; acc.z += a * bv.z; acc.w += a * bv.w;
    }
    float4 o;
    if (R) {
        float4 r = *(const float4*)&R[i * 36 + jq];
        o.x = c0 * acc.x + c1 * r.x; o.y = c0 * acc.y + c1 * r.y;
        o.z = c0 * acc.z + c1 * r.z; o.w = c0 * acc.w + c1 * r.w;
    } else {
        o.x = c0 * acc.x; o.y = c0 * acc.y; o.z = c0 * acc.z; o.w = c0 * acc.w;
    }
    *(float4*)&C[i * 36 + jq] = o;
}

// D2: per batch b: Z = pinv(S) via 6 Newton-Schulz iters (smem), then
// out = (S@Z@S) @ V written to AO[(f*1024+b)*192 + c].
__global__ __launch_bounds__(256) void depth_pinv_out_kernel(
    const float* __restrict__ Sin, const float* __restrict__ qkv,
    float* __restrict__ AO, const float* __restrict__ smax)
{
    extern __shared__ float sm[];
    // 6 mats of [32][36] then V [32][192]
    float* M0 = sm;                 // S
    float* vb = sm + 6 * 1152;      // V
    int b = blockIdx.x, tid = threadIdx.x;
    // load S
    {
        int f = tid >> 3, j4 = (tid & 7) * 4;
        float4 sv = *(const float4*)&Sin[(long)b * 1024 + f * 32 + j4];
        *(float4*)&M0[f * 36 + j4] = sv;
    }
    // load V
    for (int t = 0; t < 6; t++) {
        int idx = tid + t * 256;
        int f = idx / 48, c4 = (idx % 48) * 4;
        float4 vv = *(const float4*)&qkv[((long)f * 1024 + b) * 576 + 384 + c4];
        *(float4*)&vb[f * 192 + c4] = vv;
    }
    __syncthreads();
    // init z0 = S^T * (1/(smax0*smax1))
    float sc = 1.f / (smax[0] * smax[1]);
    int zi = 1, zf = 2;   // buffer indices for Z / free
    {
        int i = tid >> 3, jq = (tid & 7) * 4;
        float* Z = sm + zi * 1152;
        float4 o;
        o.x = M0[(jq + 0) * 36 + i] * sc; o.y = M0[(jq + 1) * 36 + i] * sc;
        o.z = M0[(jq + 2) * 36 + i] * sc; o.w = M0[(jq + 3) * 36 + i] * sc;
        *(float4*)&Z[i * 36 + jq] = o;
    }
    __syncthreads();
    float* T1 = sm + 3 * 1152;
    float* T2 = sm + 4 * 1152;
    float* T3 = sm + 5 * 1152;
    for (int it = 0; it < 6; it++) {
        float* Z  = sm + zi * 1152;
        float* Zo = sm + zf * 1152;
        mm32(M0, Z, T1, 0, 1.f, 0.f, tid);            __syncthreads();
        mm32(T1, T1, T2, T1, -1.f, 7.f, tid);         __syncthreads();
        mm32(T1, T2, T3, T1, -1.f, 15.f, tid);        __syncthreads();
        mm32(Z, T3, Zo, Z, -0.25f, 3.25f, tid);       __syncthreads();
        int t = zi; zi = zf; zf = t;
    }
    float* Z = sm + zi * 1152;
    // P1 = S@Z (T1), P2 = P1@S (T2)
    mm32(M0, Z, T1, 0, 1.f, 0.f, tid);  __syncthreads();
    mm32(T1, M0, T2, 0, 1.f, 0.f, tid); __syncthreads();
    // out = P2 @ V  -> global, row f = i
    {
        int i = tid >> 3, cq = (tid & 7) * 24;
        float4 acc[6];
        #pragma unroll
        for (int t = 0; t < 6; t++) acc[t] = make_float4(0.f, 0.f, 0.f, 0.f);
        for (int j = 0; j < 32; j++) {
            float s = T2[i * 36 + j];
            #pragma unroll
            for (int t = 0; t < 6; t++) {
                float4 vv = *(float4*)&vb[j * 192 + cq + t * 4];
                acc[t].x += s * vv.x; acc[t].y += s * vv.y;
                acc[t].z += s * vv.z; acc[t].w += s * vv.w;
            }
        }
        long base = ((long)i * 1024 + b) * 192 + cq;
        #pragma unroll
        for (int t = 0; t < 6; t++) *(float4*)&AO[base + t * 4] = acc[t];
    }
}

// ------------------------- small kernels ------------------------------------

__global__ void scale_norm_kernel(const float* __restrict__ x, float* __restrict__ y,
                                  const float* __restrict__ g, int gidx, int rows)
{
    int row = blockIdx.x * 8 + (threadIdx.x >> 5);
    if (row >= rows) return;
    int lane = threadIdx.x & 31;
    const float* xr = x + (long)row * DIMM;
    float v[6]; float ss = 0.f;
    #pragma unroll
    for (int t = 0; t < 6; t++) { v[t] = xr[lane + 32 * t]; ss += v[t] * v[t]; }
    #pragma unroll
    for (int o = 16; o > 0; o >>= 1) ss += __shfl_xor_sync(0xffffffffu, ss, o);
    float nrm = fmaxf(sqrtf(ss), 1e-5f);
    float s = g[gidx] / nrm;
    float* yr = y + (long)row * DIMM;
    #pragma unroll
    for (int t = 0; t < 6; t++) yr[lane + 32 * t] = v[t] * s;
}

__global__ void softmax_kernel(float* __restrict__ Sm, long rows, int n)
{
    long row = (long)blockIdx.x * 8 + (threadIdx.x >> 5);
    if (row >= rows) return;
    int lane = threadIdx.x & 31;
    float* p = Sm + row * n;
    float mx = -1e30f;
    for (int j = lane; j < n; j += 32) mx = fmaxf(mx, p[j]);
    #pragma unroll
    for (int o = 16; o > 0; o >>= 1) mx = fmaxf(mx, __shfl_xor_sync(0xffffffffu, mx, o));
    float sum = 0.f;
    for (int j = lane; j < n; j += 32) { float e = expf(p[j] - mx); p[j] = e; sum += e; }
    #pragma unroll
    for (int o = 16; o > 0; o >>= 1) sum += __shfl_xor_sync(0xffffffffu, sum, o);
    float inv = 1.f / sum;
    for (int j = lane; j < n; j += 32) p[j] *= inv;
}

__global__ void landmark_kernel(const float* __restrict__ qkv,
                                float* __restrict__ qL, float* __restrict__ kL)
{
    int idx = blockIdx.x * blockDim.x + threadIdx.x;
    if (idx >= 32 * 256 * 192) return;
    int c = idx % 192;
    int j = (idx / 192) & 255;
    int f = idx / (192 * 256);
    long base = ((long)f * 1024 + j * 4) * 576;
    float sq = 0.f, sk = 0.f;
    #pragma unroll
    for (int t = 0; t < 4; t++) {
        sq += qkv[base + (long)t * 576 + c];
        sk += qkv[base + (long)t * 576 + 192 + c];
    }
    qL[idx] = sq * 0.25f;
    kL[idx] = sk * 0.25f;
}

__global__ void zero2_kernel(float* p) { if (threadIdx.x < 2) p[threadIdx.x] = 0.f; }

__global__ void rowabs_max_kernel(const float* __restrict__ Sm, float* smax, long rows, int n)
{
    long row = (long)blockIdx.x * 8 + (threadIdx.x >> 5);
    if (row >= rows) return;
    int lane = threadIdx.x & 31;
    const float* p = Sm + row * n;
    float s = 0.f;
    for (int j = lane; j < n; j += 32) s += fabsf(p[j]);
    #pragma unroll
    for (int o = 16; o > 0; o >>= 1) s += __shfl_xor_sync(0xffffffffu, s, o);
    if (lane == 0) atomicMax((int*)smax, __float_as_int(s));
}

__global__ void colabs_max_kernel(const float* __restrict__ Sm, float* smax, int batch, int n)
{
    int t = blockIdx.x * blockDim.x + threadIdx.x;
    if (t >= batch * n) return;
    int b = t / n, j = t % n;
    const float* p = Sm + (long)b * n * n + j;
    float s = 0.f;
    for (int i = 0; i < n; i++) s += fabsf(p[(long)i * n]);
    atomicMax((int*)(smax + 1), __float_as_int(s));
}

__global__ void transpose_scale_kernel(const float* __restrict__ Sm, float* __restrict__ Z,
                                       const float* smax, int n)
{
    __shared__ float tile[32][33];
    int b = blockIdx.z;
    int x0 = blockIdx.x * 32, y0 = blockIdx.y * 32;
    const float* Sb = Sm + (long)b * n * n;
    tile[threadIdx.y][threadIdx.x] = Sb[(long)(y0 + threadIdx.y) * n + x0 + threadIdx.x];
    __syncthreads();
    float s = 1.0f / (smax[0] * smax[1]);
    Z[(long)b * n * n + (long)(x0 + threadIdx.y) * n + y0 + threadIdx.x] =
        tile[threadIdx.x][threadIdx.y] * s;
}

__global__ void geglu_kernel(const float* __restrict__ h, float* __restrict__ hg)
{
    long idx = (long)blockIdx.x * blockDim.x + threadIdx.x;
    if (idx >= (long)S_TOT * 768) return;
    long m = idx / 768; int j = (int)(idx % 768);
    float a  = h[m * 1536 + j];
    float gt = h[m * 1536 + 768 + j];
    float gl = 0.5f * gt * (1.0f + erff(gt * 0.70710678118654752f));
    hg[idx] = a * gl;
}

__global__ void patchify_kernel(const float* __restrict__ vol, float* __restrict__ vp)
{
    long idx = (long)blockIdx.x * blockDim.x + threadIdx.x;
    if (idx >= (long)S_TOT * DIMM) return;
    int s = (int)(idx / DIMM);
    int k = (int)(idx % DIMM);
    int d = s >> 10;
    int h = (s >> 5) & 31;
    int w = s & 31;
    int p1 = k / 24; int r = k % 24; int p2 = r / 3; int c = r % 3;
    vp[idx] = vol[(((long)c * 32 + d) * 256 + h * 8 + p1) * 256 + w * 8 + p2];
}

// ------------------------- host orchestration --------------------------------

static void g256(const float* A, long sAb, long sAr,
                 const float* B, long sBb, long sBr, int tB,
                 float* C, long sCb, long sCr,
                 int batch, int M, int N, int K, float c0,
                 const float* bias, const float* resid, long sRb, long sRr, float c1)
{
    dim3 grid(N / 64, M / 256, batch);
    gemm256_kernel<<<grid, 256>>>(A, B, C, M, N, K, sAb, sAr, sBb, sBr, sCb, sCr,
                                  tB, c0, bias, resid, sRb, sRr, c1);
}

static void softmax_rows(float* p, long rows, int n)
{
    softmax_kernel<<<(int)((rows + 7) / 8), 256>>>(p, rows, n);
}

#define GETSYM(var, sym) do { void* _p; cudaGetSymbolAddress(&_p, sym); var = (float*)_p; } while (0)

extern "C" void kernel_launch(void* const* d_in, const int* in_sizes, int n_in,
                              void* d_out, int out_size)
{
    (void)in_sizes; (void)n_in; (void)out_size;
    const float* volume      = (const float*)d_in[0];
    const float* patch_w     = (const float*)d_in[1];
    const float* patch_b     = (const float*)d_in[2];
    const float* pos_emb     = (const float*)d_in[3];
    const float* gd          = (const float*)d_in[4];
    const float* qkv_depth   = (const float*)d_in[5];
    const float* outw_depth  = (const float*)d_in[6];
    const float* outb_depth  = (const float*)d_in[7];
    const float* gs          = (const float*)d_in[8];
    const float* qkv_spatial = (const float*)d_in[9];
    const float* outw_spatial= (const float*)d_in[10];
    const float* outb_spatial= (const float*)d_in[11];
    const float* gf          = (const float*)d_in[12];
    const float* ff_w1       = (const float*)d_in[13];
    const float* ff_b1       = (const float*)d_in[14];
    const float* ff_w2       = (const float*)d_in[15];
    const float* ff_b2       = (const float*)d_in[16];
    const float* g_final     = (const float*)d_in[17];

    float *X, *XN, *QKV, *AO, *A1, *A2, *A3, *QL, *KL, *Z0, *Z1, *T1, *T2, *T3, *AV, *W2, *H, *HG, *SMAX;
    GETSYM(X, g_x);   GETSYM(XN, g_xn); GETSYM(QKV, g_qkv); GETSYM(AO, g_ao);
    GETSYM(A1, g_a1); GETSYM(A2, g_a2); GETSYM(A3, g_a3);
    GETSYM(QL, g_ql); GETSYM(KL, g_kl);
    GETSYM(Z0, g_Z0); GETSYM(Z1, g_Z1); GETSYM(T1, g_T1); GETSYM(T2, g_T2); GETSYM(T3, g_T3);
    GETSYM(AV, g_av); GETSYM(W2, g_w2); GETSYM(H, g_h);   GETSYM(HG, g_hg);
    GETSYM(SMAX, g_smax);

    const int DSM = 13056 * 4;  // dynamic smem for depth kernels (52224 B)
    cudaFuncSetAttribute(depth_scores_kernel,  cudaFuncAttributeMaxDynamicSharedMemorySize, DSM);
    cudaFuncSetAttribute(depth_pinv_out_kernel, cudaFuncAttributeMaxDynamicSharedMemorySize, DSM);

    const float SCALE = 0.0721687836487032f; // 192^-0.5

    // ---- patch embed: x = patchify(vol) @ patch_w + patch_b + pos_emb
    {
        long tot = (long)S_TOT * DIMM;
        patchify_kernel<<<(int)((tot + 255) / 256), 256>>>(volume, XN);
        g256(XN, 0, 192, patch_w, 0, 192, 0, X, 0, 192, 1, S_TOT, 192, 192, 1.f,
             patch_b, pos_emb, 0, 192, 1.f);
    }

    for (int i = 0; i < NLAYERS; i++) {
        const float* Wqkv_d = qkv_depth   + (long)i * DIMM * 3 * DIMM;
        const float* Wout_d = outw_depth  + (long)i * DIMM * DIMM;
        const float* bout_d = outb_depth  + (long)i * DIMM;
        const float* Wqkv_s = qkv_spatial + (long)i * DIMM * 3 * DIMM;
        const float* Wout_s = outw_spatial+ (long)i * DIMM * DIMM;
        const float* bout_s = outb_spatial+ (long)i * DIMM;
        const float* W1     = ff_w1 + (long)i * DIMM * 8 * DIMM;
        const float* B1     = ff_b1 + (long)i * 8 * DIMM;
        const float* W2w    = ff_w2 + (long)i * 4 * DIMM * DIMM;
        const float* B2     = ff_b2 + (long)i * DIMM;

        // ================= depth attention (fused) ===========================
        scale_norm_kernel<<<S_TOT / 8, 256>>>(X, XN, gd, i, S_TOT);
        g256(XN, 0, 192, Wqkv_d, 0, 576, 0, QKV, 0, 576, 1, S_TOT, 576, 192, 1.f,
             0, 0, 0, 0, 0.f);
        depth_scores_kernel<<<1024, 256, DSM>>>(QKV, A2);
        zero2_kernel<<<1, 32>>>(SMAX);
        rowabs_max_kernel<<<(1024 * 32 + 7) / 8, 256>>>(A2, SMAX, (long)1024 * 32, 32);
        colabs_max_kernel<<<(1024 * 32 + 255) / 256, 256>>>(A2, SMAX, 1024, 32);
        depth_pinv_out_kernel<<<1024, 256, DSM>>>(A2, QKV, AO, SMAX);
        g256(AO, 0, 192, Wout_d, 0, 192, 0, X, 0, 192, 1, S_TOT, 192, 192, 1.f,
             bout_d, X, 0, 192, 1.f);

        // ================= spatial attention (batch=32, n=1024, m=256) ======
        scale_norm_kernel<<<S_TOT / 8, 256>>>(X, XN, gs, i, S_TOT);
        g256(XN, 0, 192, Wqkv_s, 0, 576, 0, QKV, 0, 576, 1, S_TOT, 576, 192, 1.f,
             0, 0, 0, 0, 0.f);
        landmark_kernel<<<(32 * 256 * 192 + 255) / 256, 256>>>(QKV, QL, KL);
        // a1 = softmax(SCALE * q @ kL^T)  [32,1024,256]
        g256(QKV, (long)1024 * 576, 576, KL, 256 * 192, 192, 1,
             A1, (long)1024 * 256, 256, 32, 1024, 256, 192, SCALE, 0, 0, 0, 0, 0.f);
        // a2 = softmax(SCALE * qL @ kL^T) [32,256,256]
        g256(QL, 256 * 192, 192, KL, 256 * 192, 192, 1,
             A2, 256 * 256, 256, 32, 256, 256, 192, SCALE, 0, 0, 0, 0, 0.f);
        // a3 = softmax(SCALE * qL @ k^T)  [32,256,1024]
        g256(QL, 256 * 192, 192, QKV + 192, (long)1024 * 576, 576, 1,
             A3, (long)256 * 1024, 1024, 32, 256, 1024, 192, SCALE, 0, 0, 0, 0, 0.f);
        softmax_rows(A1, (long)32 * 1024, 256);
        softmax_rows(A2, (long)32 * 256, 256);
        softmax_rows(A3, (long)32 * 256, 1024);
        // pinv(a2), n=256
        zero2_kernel<<<1, 32>>>(SMAX);
        rowabs_max_kernel<<<(32 * 256 + 7) / 8, 256>>>(A2, SMAX, (long)32 * 256, 256);
        colabs_max_kernel<<<(32 * 256 + 255) / 256, 256>>>(A2, SMAX, 32, 256);
        {
            dim3 tg(8, 8, 32);
            transpose_scale_kernel<<<tg, dim3(32, 32)>>>(A2, Z0, SMAX, 256);
        }
        float* Zc = Z0; float* Zn = Z1;
        const long nn = 256 * 256;
        for (int it = 0; it < 6; it++) {
            g256(A2, nn, 256, Zc, nn, 256, 0, T1, nn, 256, 32, 256, 256, 256, 1.f,
                 0, 0, 0, 0, 0.f);
            g256(T1, nn, 256, T1, nn, 256, 0, T2, nn, 256, 32, 256, 256, 256, -1.f,
                 0, T1, nn, 256, 7.f);
            g256(T1, nn, 256, T2, nn, 256, 0, T3, nn, 256, 32, 256, 256, 256, -1.f,
                 0, T1, nn, 256, 15.f);
            g256(Zc, nn, 256, T3, nn, 256, 0, Zn, nn, 256, 32, 256, 256, 256, -0.25f,
                 0, Zc, nn, 256, 3.25f);
            float* t = Zc; Zc = Zn; Zn = t;
        }
        // a3v = a3 @ v  [32,256,192]
        g256(A3, (long)256 * 1024, 1024, QKV + 384, (long)1024 * 576, 576, 0,
             AV, 256 * 192, 192, 32, 256, 192, 1024, 1.f, 0, 0, 0, 0, 0.f);
        // w = Z @ a3v
        g256(Zc, nn, 256, AV, 256 * 192, 192, 0,
             W2, 256 * 192, 192, 32, 256, 192, 256, 1.f, 0, 0, 0, 0, 0.f);
        // out = a1 @ w
        g256(A1, (long)1024 * 256, 256, W2, 256 * 192, 192, 0,
             AO, (long)1024 * 192, 192, 32, 1024, 192, 256, 1.f, 0, 0, 0, 0, 0.f);
        g256(AO, 0, 192, Wout_s, 0, 192, 0, X, 0, 192, 1, S_TOT, 192, 192, 1.f,
             bout_s, X, 0, 192, 1.f);

        // ================= GEGLU feed-forward ================================
        scale_norm_kernel<<<S_TOT / 8, 256>>>(X, XN, gf, i, S_TOT);
        g256(XN, 0, 192, W1, 0, 1536, 0, H, 0, 1536, 1, S_TOT, 1536, 192, 1.f,
             B1, 0, 0, 0, 0.f);
        geglu_kernel<<<(int)(((long)S_TOT * 768 + 255) / 256), 256>>>(H, HG);
        g256(HG, 0, 768, W2w, 0, 192, 0, X, 0, 192, 1, S_TOT, 192, 768, 1.f,
             B2, X, 0, 192, 1.f);
    }

    // ---- final scale norm -> output
    scale_norm_kernel<<<S_TOT / 8, 256>>>(X, (float*)d_out, g_final, 0, S_TOT);
}

// round 15
// speedup vs baseline: 2.0562x; 1.1860x over previous
#include <cuda_runtime.h>
#include <math.h>

// ---------------------------------------------------------------------------
// DepthFormer forward, fp32. S=32768 tokens, dim=192, 4 layers.
// R6: 128x64 double-buffered GEMM (8x4 micro-tile, 2 CTA/SM) + fused depth attn.
// ---------------------------------------------------------------------------

#define S_TOT 32768
#define DIMM 192
#define NLAYERS 4

// ------------------------- scratch (device globals) ------------------------
__device__ float g_x [S_TOT * DIMM];
__device__ float g_xn[S_TOT * DIMM];
__device__ float g_qkv[S_TOT * 3 * DIMM];
__device__ float g_ao[S_TOT * DIMM];
__device__ float g_a1[32 * 1024 * 256];
__device__ float g_a3[32 * 256 * 1024];
__device__ float g_a2[32 * 256 * 256];      // spatial a2; also depth scores (1024*32*32)
__device__ float g_ql[32 * 256 * 192];
__device__ float g_kl[32 * 256 * 192];
__device__ float g_Z0[32 * 256 * 256];
__device__ float g_Z1[32 * 256 * 256];
__device__ float g_T1[32 * 256 * 256];
__device__ float g_T2[32 * 256 * 256];
__device__ float g_T3[32 * 256 * 256];
__device__ float g_av[32 * 256 * 192];
__device__ float g_w2[32 * 256 * 192];
__device__ float g_h [S_TOT * 8 * DIMM];
__device__ float g_hg[S_TOT * 4 * DIMM];
__device__ float g_smax[2];

// ---------------------------------------------------------------------------
// Unified GEMM: C[b,m,n] = c0 * A[b]@B[b] (+bias[n]) (+c1*resid[b,m,n])
// Tile 128x64x16, 256 threads, 8x4 micro-tile, double-buffered smem,
// register prefetch, one __syncthreads per K-step. 2 CTAs/SM target.
// Requires M%128==0, N%64==0, K%16==0, row strides %4, 16B-aligned bases.
// ---------------------------------------------------------------------------
#define APAD 132
#define BPAD 68

#define LOAD_TILE(k0) do {                                                          \
    _Pragma("unroll")                                                               \
    for (int t = 0; t < 2; t++) {                                                   \
        int idx = tid + t * 256;                                                    \
        pa[t] = *(const float4*)&Ab[(bm + (idx >> 2)) * sAr + (k0) + (idx & 3) * 4];\
    }                                                                               \
    if (!transB)                                                                    \
        pb = *(const float4*)&Bb[(long)((k0) + (tid >> 4)) * sBr + bn + (tid & 15) * 4]; \
    else                                                                            \
        pb = *(const float4*)&Bb[(bn + (tid >> 2)) * sBr + (k0) + (tid & 3) * 4];   \
} while (0)

#define STORE_STAGE(st) do {                                                        \
    _Pragma("unroll")                                                               \
    for (int t = 0; t < 2; t++) {                                                   \
        int idx = tid + t * 256;                                                    \
        int row = idx >> 2, k4 = (idx & 3) * 4;                                     \
        As[st][(k4 + 0) * APAD + row] = pa[t].x;                                    \
        As[st][(k4 + 1) * APAD + row] = pa[t].y;                                    \
        As[st][(k4 + 2) * APAD + row] = pa[t].z;                                    \
        As[st][(k4 + 3) * APAD + row] = pa[t].w;                                    \
    }                                                                               \
    if (!transB) {                                                                  \
        *(float4*)&Bs[st][(tid >> 4) * BPAD + (tid & 15) * 4] = pb;                 \
    } else {                                                                        \
        int n = tid >> 2, k4 = (tid & 3) * 4;                                       \
        Bs[st][(k4 + 0) * BPAD + n] = pb.x;                                         \
        Bs[st][(k4 + 1) * BPAD + n] = pb.y;                                         \
        Bs[st][(k4 + 2) * BPAD + n] = pb.z;                                         \
        Bs[st][(k4 + 3) * BPAD + n] = pb.w;                                         \
    }                                                                               \
} while (0)

__global__ __launch_bounds__(256) void gemm128_kernel(
    const float* __restrict__ A, const float* __restrict__ B, float* __restrict__ C,
    int M, int N, int K,
    long sAb, long sAr, long sBb, long sBr, long sCb, long sCr,
    int transB, float c0,
    const float* __restrict__ bias,
    const float* __restrict__ resid, long sRb, long sRr, float c1)
{
    __shared__ float As[2][16 * APAD];
    __shared__ float Bs[2][16 * BPAD];
    int b = blockIdx.z;
    long bm = (long)blockIdx.y * 128, bn = (long)blockIdx.x * 64;
    const float* Ab = A + (long)b * sAb;
    const float* Bb = B + (long)b * sBb;
    int tid = threadIdx.x;
    int ty = tid >> 4, tx = tid & 15;   // rows ty*8..+8, cols tx*4..+4

    float4 pa[2]; float4 pb;
    float acc[8][4] = {};

    LOAD_TILE(0);
    STORE_STAGE(0);
    __syncthreads();

    int st = 0;
    for (int k0 = 0; k0 < K; k0 += 16) {
        bool more = (k0 + 16) < K;
        if (more) LOAD_TILE(k0 + 16);
        #pragma unroll
        for (int k = 0; k < 16; k++) {
            float4 a0 = *(float4*)&As[st][k * APAD + ty * 8];
            float4 a1 = *(float4*)&As[st][k * APAD + ty * 8 + 4];
            float4 bq = *(float4*)&Bs[st][k * BPAD + tx * 4];
            float av[8] = {a0.x, a0.y, a0.z, a0.w, a1.x, a1.y, a1.z, a1.w};
            float bv[4] = {bq.x, bq.y, bq.z, bq.w};
            #pragma unroll
            for (int u = 0; u < 8; u++)
                #pragma unroll
                for (int v = 0; v < 4; v++)
                    acc[u][v] += av[u] * bv[v];
        }
        if (more) {
            STORE_STAGE(st ^ 1);
            __syncthreads();
            st ^= 1;
        }
    }

    float4 bv0 = make_float4(0.f, 0.f, 0.f, 0.f);
    if (bias) bv0 = *(const float4*)&bias[bn + tx * 4];
    #pragma unroll
    for (int u = 0; u < 8; u++) {
        long m = bm + ty * 8 + u;
        float4 o;
        o.x = c0 * acc[u][0] + bv0.x; o.y = c0 * acc[u][1] + bv0.y;
        o.z = c0 * acc[u][2] + bv0.z; o.w = c0 * acc[u][3] + bv0.w;
        if (resid) {
            float4 r = *(const float4*)&resid[(long)b * sRb + m * sRr + bn + tx * 4];
            o.x += c1 * r.x; o.y += c1 * r.y; o.z += c1 * r.z; o.w += c1 * r.w;
        }
        *(float4*)&C[(long)b * sCb + m * sCr + bn + tx * 4] = o;
    }
}

// ---------------------------------------------------------------------------
// Depth attention fused kernels. batch b = spatial patch index (0..1023),
// sequence = 32 depth slices. qkv row for (f, b) at QKV[(f*1024+b)*576].
// ---------------------------------------------------------------------------

// D1: S = softmax(SCALE * q @ k^T) per batch -> A2[b*1024 + i*32 + j]
__global__ __launch_bounds__(256) void depth_scores_kernel(
    const float* __restrict__ qkv, float* __restrict__ Sout)
{
    extern __shared__ float sm[];
    float* qb = sm;            // [32][192]
    float* kT = sm + 6144;     // [192][36]
    int b = blockIdx.x, tid = threadIdx.x;
    for (int t = 0; t < 6; t++) {
        int idx = tid + t * 256;          // 0..1535 float4s
        int f = idx / 48, c4 = (idx % 48) * 4;
        long base = ((long)f * 1024 + b) * 576 + c4;
        float4 qv = *(const float4*)&qkv[base];
        float4 kv = *(const float4*)&qkv[base + 192];
        *(float4*)&qb[f * 192 + c4] = qv;
        kT[(c4 + 0) * 36 + f] = kv.x; kT[(c4 + 1) * 36 + f] = kv.y;
        kT[(c4 + 2) * 36 + f] = kv.z; kT[(c4 + 3) * 36 + f] = kv.w;
    }
    __syncthreads();
    int i = tid >> 3, jq = (tid & 7) * 4;
    float4 acc = make_float4(0.f, 0.f, 0.f, 0.f);
    for (int c = 0; c < 192; c++) {
        float qv = qb[i * 192 + c];
        float4 kv = *(float4*)&kT[c * 36 + jq];
        acc.x += qv * kv.x; acc.y += qv * kv.y; acc.z += qv * kv.z; acc.w += qv * kv.w;
    }
    const float SCALE = 0.0721687836487032f;
    acc.x *= SCALE; acc.y *= SCALE; acc.z *= SCALE; acc.w *= SCALE;
    float mx = fmaxf(fmaxf(acc.x, acc.y), fmaxf(acc.z, acc.w));
    #pragma unroll
    for (int o = 4; o > 0; o >>= 1) mx = fmaxf(mx, __shfl_xor_sync(0xffffffffu, mx, o));
    acc.x = expf(acc.x - mx); acc.y = expf(acc.y - mx);
    acc.z = expf(acc.z - mx); acc.w = expf(acc.w - mx);
    float sum = acc.x + acc.y + acc.z + acc.w;
    #pragma unroll
    for (int o = 4; o > 0; o >>= 1) sum += __shfl_xor_sync(0xffffffffu, sum, o);
    float inv = 1.f / sum;
    acc.x *= inv; acc.y *= inv; acc.z *= inv; acc.w *= inv;
    *(float4*)&Sout[(long)b * 1024 + i * 32 + jq] = acc;
}

// 32x32 smem matmul helper: C = c0*A@B + c1*R  (all [32][36] smem, 256 thr)
__device__ __forceinline__ void mm32(const float* __restrict__ A, const float* __restrict__ B,
                                     float* __restrict__ C, const float* __restrict__ R,
                                     float c0, float c1, int tid)
{
    int i = tid >> 3, jq = (tid & 7) * 4;
    float4 acc = make_float4(0.f, 0.f, 0.f, 0.f);
    #pragma unroll 8
    for (int k = 0; k < 32; k++) {
        float a = A[i * 36 + k];
        float4 bv = *(const float4*)&B[k * 36 + jq];
        acc.x += a * bv.x; acc.y += a * bv.y; acc.z += a * bv.z; acc.w += a * bv.w;
    }
    float4 o;
    if (R) {
        float4 r = *(const float4*)&R[i * 36 + jq];
        o.x = c0 * acc.x + c1 * r.x; o.y = c0 * acc.y + c1 * r.y;
        o.z = c0 * acc.z + c1 * r.z; o.w = c0 * acc.w + c1 * r.w;
    } else {
        o.x = c0 * acc.x; o.y = c0 * acc.y; o.z = c0 * acc.z; o.w = c0 * acc.w;
    }
    *(float4*)&C[i * 36 + jq] = o;
}

// D2: per batch b: Z = pinv(S) via 6 Newton-Schulz iters (smem), then
// out = (S@Z@S) @ V written to AO[(f*1024+b)*192 + c].
__global__ __launch_bounds__(256) void depth_pinv_out_kernel(
    const float* __restrict__ Sin, const float* __restrict__ qkv,
    float* __restrict__ AO, const float* __restrict__ smax)
{
    extern __shared__ float sm[];
    // 6 mats of [32][36] then V [32][192]
    float* M0 = sm;                 // S
    float* vb = sm + 6 * 1152;      // V
    int b = blockIdx.x, tid = threadIdx.x;
    // load S
    {
        int f = tid >> 3, j4 = (tid & 7) * 4;
        float4 sv = *(const float4*)&Sin[(long)b * 1024 + f * 32 + j4];
        *(float4*)&M0[f * 36 + j4] = sv;
    }
    // load V
    for (int t = 0; t < 6; t++) {
        int idx = tid + t * 256;
        int f = idx / 48, c4 = (idx % 48) * 4;
        float4 vv = *(const float4*)&qkv[((long)f * 1024 + b) * 576 + 384 + c4];
        *(float4*)&vb[f * 192 + c4] = vv;
    }
    __syncthreads();
    // init z0 = S^T * (1/(smax0*smax1))
    float sc = 1.f / (smax[0] * smax[1]);
    int zi = 1, zf = 2;   // buffer indices for Z / free
    {
        int i = tid >> 3, jq = (tid & 7) * 4;
        float* Z = sm + zi * 1152;
        float4 o;
        o.x = M0[(jq + 0) * 36 + i] * sc; o.y = M0[(jq + 1) * 36 + i] * sc;
        o.z = M0[(jq + 2) * 36 + i] * sc; o.w = M0[(jq + 3) * 36 + i] * sc;
        *(float4*)&Z[i * 36 + jq] = o;
    }
    __syncthreads();
    float* T1 = sm + 3 * 1152;
    float* T2 = sm + 4 * 1152;
    float* T3 = sm + 5 * 1152;
    for (int it = 0; it < 6; it++) {
        float* Z  = sm + zi * 1152;
        float* Zo = sm + zf * 1152;
        mm32(M0, Z, T1, 0, 1.f, 0.f, tid);            __syncthreads();
        mm32(T1, T1, T2, T1, -1.f, 7.f, tid);         __syncthreads();
        mm32(T1, T2, T3, T1, -1.f, 15.f, tid);        __syncthreads();
        mm32(Z, T3, Zo, Z, -0.25f, 3.25f, tid);       __syncthreads();
        int t = zi; zi = zf; zf = t;
    }
    float* Z = sm + zi * 1152;
    // P1 = S@Z (T1), P2 = P1@S (T2)
    mm32(M0, Z, T1, 0, 1.f, 0.f, tid);  __syncthreads();
    mm32(T1, M0, T2, 0, 1.f, 0.f, tid); __syncthreads();
    // out = P2 @ V  -> global, row f = i
    {
        int i = tid >> 3, cq = (tid & 7) * 24;
        float4 acc[6];
        #pragma unroll
        for (int t = 0; t < 6; t++) acc[t] = make_float4(0.f, 0.f, 0.f, 0.f);
        for (int j = 0; j < 32; j++) {
            float s = T2[i * 36 + j];
            #pragma unroll
            for (int t = 0; t < 6; t++) {
                float4 vv = *(float4*)&vb[j * 192 + cq + t * 4];
                acc[t].x += s * vv.x; acc[t].y += s * vv.y;
                acc[t].z += s * vv.z; acc[t].w += s * vv.w;
            }
        }
        long base = ((long)i * 1024 + b) * 192 + cq;
        #pragma unroll
        for (int t = 0; t < 6; t++) *(float4*)&AO[base + t * 4] = acc[t];
    }
}

// ------------------------- small kernels ------------------------------------

__global__ void scale_norm_kernel(const float* __restrict__ x, float* __restrict__ y,
                                  const float* __restrict__ g, int gidx, int rows)
{
    int row = blockIdx.x * 8 + (threadIdx.x >> 5);
    if (row >= rows) return;
    int lane = threadIdx.x & 31;
    const float* xr = x + (long)row * DIMM;
    float v[6]; float ss = 0.f;
    #pragma unroll
    for (int t = 0; t < 6; t++) { v[t] = xr[lane + 32 * t]; ss += v[t] * v[t]; }
    #pragma unroll
    for (int o = 16; o > 0; o >>= 1) ss += __shfl_xor_sync(0xffffffffu, ss, o);
    float nrm = fmaxf(sqrtf(ss), 1e-5f);
    float s = g[gidx] / nrm;
    float* yr = y + (long)row * DIMM;
    #pragma unroll
    for (int t = 0; t < 6; t++) yr[lane + 32 * t] = v[t] * s;
}

__global__ void softmax_kernel(float* __restrict__ Sm, long rows, int n)
{
    long row = (long)blockIdx.x * 8 + (threadIdx.x >> 5);
    if (row >= rows) return;
    int lane = threadIdx.x & 31;
    float* p = Sm + row * n;
    float mx = -1e30f;
    for (int j = lane; j < n; j += 32) mx = fmaxf(mx, p[j]);
    #pragma unroll
    for (int o = 16; o > 0; o >>= 1) mx = fmaxf(mx, __shfl_xor_sync(0xffffffffu, mx, o));
    float sum = 0.f;
    for (int j = lane; j < n; j += 32) { float e = expf(p[j] - mx); p[j] = e; sum += e; }
    #pragma unroll
    for (int o = 16; o > 0; o >>= 1) sum += __shfl_xor_sync(0xffffffffu, sum, o);
    float inv = 1.f / sum;
    for (int j = lane; j < n; j += 32) p[j] *= inv;
}

__global__ void landmark_kernel(const float* __restrict__ qkv,
                                float* __restrict__ qL, float* __restrict__ kL)
{
    int idx = blockIdx.x * blockDim.x + threadIdx.x;
    if (idx >= 32 * 256 * 192) return;
    int c = idx % 192;
    int j = (idx / 192) & 255;
    int f = idx / (192 * 256);
    long base = ((long)f * 1024 + j * 4) * 576;
    float sq = 0.f, sk = 0.f;
    #pragma unroll
    for (int t = 0; t < 4; t++) {
        sq += qkv[base + (long)t * 576 + c];
        sk += qkv[base + (long)t * 576 + 192 + c];
    }
    qL[idx] = sq * 0.25f;
    kL[idx] = sk * 0.25f;
}

__global__ void zero2_kernel(float* p) { if (threadIdx.x < 2) p[threadIdx.x] = 0.f; }

__global__ void rowabs_max_kernel(const float* __restrict__ Sm, float* smax, long rows, int n)
{
    long row = (long)blockIdx.x * 8 + (threadIdx.x >> 5);
    if (row >= rows) return;
    int lane = threadIdx.x & 31;
    const float* p = Sm + row * n;
    float s = 0.f;
    for (int j = lane; j < n; j += 32) s += fabsf(p[j]);
    #pragma unroll
    for (int o = 16; o > 0; o >>= 1) s += __shfl_xor_sync(0xffffffffu, s, o);
    if (lane == 0) atomicMax((int*)smax, __float_as_int(s));
}

__global__ void colabs_max_kernel(const float* __restrict__ Sm, float* smax, int batch, int n)
{
    int t = blockIdx.x * blockDim.x + threadIdx.x;
    if (t >= batch * n) return;
    int b = t / n, j = t % n;
    const float* p = Sm + (long)b * n * n + j;
    float s = 0.f;
    for (int i = 0; i < n; i++) s += fabsf(p[(long)i * n]);
    atomicMax((int*)(smax + 1), __float_as_int(s));
}

__global__ void transpose_scale_kernel(const float* __restrict__ Sm, float* __restrict__ Z,
                                       const float* smax, int n)
{
    __shared__ float tile[32][33];
    int b = blockIdx.z;
    int x0 = blockIdx.x * 32, y0 = blockIdx.y * 32;
    const float* Sb = Sm + (long)b * n * n;
    tile[threadIdx.y][threadIdx.x] = Sb[(long)(y0 + threadIdx.y) * n + x0 + threadIdx.x];
    __syncthreads();
    float s = 1.0f / (smax[0] * smax[1]);
    Z[(long)b * n * n + (long)(x0 + threadIdx.y) * n + y0 + threadIdx.x] =
        tile[threadIdx.x][threadIdx.y] * s;
}

__global__ void geglu_kernel(const float* __restrict__ h, float* __restrict__ hg)
{
    long idx = (long)blockIdx.x * blockDim.x + threadIdx.x;
    if (idx >= (long)S_TOT * 768) return;
    long m = idx / 768; int j = (int)(idx % 768);
    float a  = h[m * 1536 + j];
    float gt = h[m * 1536 + 768 + j];
    float gl = 0.5f * gt * (1.0f + erff(gt * 0.70710678118654752f));
    hg[idx] = a * gl;
}

__global__ void patchify_kernel(const float* __restrict__ vol, float* __restrict__ vp)
{
    long idx = (long)blockIdx.x * blockDim.x + threadIdx.x;
    if (idx >= (long)S_TOT * DIMM) return;
    int s = (int)(idx / DIMM);
    int k = (int)(idx % DIMM);
    int d = s >> 10;
    int h = (s >> 5) & 31;
    int w = s & 31;
    int p1 = k / 24; int r = k % 24; int p2 = r / 3; int c = r % 3;
    vp[idx] = vol[(((long)c * 32 + d) * 256 + h * 8 + p1) * 256 + w * 8 + p2];
}

// ------------------------- host orchestration --------------------------------

static void g128(const float* A, long sAb, long sAr,
                 const float* B, long sBb, long sBr, int tB,
                 float* C, long sCb, long sCr,
                 int batch, int M, int N, int K, float c0,
                 const float* bias, const float* resid, long sRb, long sRr, float c1)
{
    dim3 grid(N / 64, M / 128, batch);
    gemm128_kernel<<<grid, 256>>>(A, B, C, M, N, K, sAb, sAr, sBb, sBr, sCb, sCr,
                                  tB, c0, bias, resid, sRb, sRr, c1);
}

static void softmax_rows(float* p, long rows, int n)
{
    softmax_kernel<<<(int)((rows + 7) / 8), 256>>>(p, rows, n);
}

#define GETSYM(var, sym) do { void* _p; cudaGetSymbolAddress(&_p, sym); var = (float*)_p; } while (0)

extern "C" void kernel_launch(void* const* d_in, const int* in_sizes, int n_in,
                              void* d_out, int out_size)
{
    (void)in_sizes; (void)n_in; (void)out_size;
    const float* volume      = (const float*)d_in[0];
    const float* patch_w     = (const float*)d_in[1];
    const float* patch_b     = (const float*)d_in[2];
    const float* pos_emb     = (const float*)d_in[3];
    const float* gd          = (const float*)d_in[4];
    const float* qkv_depth   = (const float*)d_in[5];
    const float* outw_depth  = (const float*)d_in[6];
    const float* outb_depth  = (const float*)d_in[7];
    const float* gs          = (const float*)d_in[8];
    const float* qkv_spatial = (const float*)d_in[9];
    const float* outw_spatial= (const float*)d_in[10];
    const float* outb_spatial= (const float*)d_in[11];
    const float* gf          = (const float*)d_in[12];
    const float* ff_w1       = (const float*)d_in[13];
    const float* ff_b1       = (const float*)d_in[14];
    const float* ff_w2       = (const float*)d_in[15];
    const float* ff_b2       = (const float*)d_in[16];
    const float* g_final     = (const float*)d_in[17];

    float *X, *XN, *QKV, *AO, *A1, *A2, *A3, *QL, *KL, *Z0, *Z1, *T1, *T2, *T3, *AV, *W2, *H, *HG, *SMAX;
    GETSYM(X, g_x);   GETSYM(XN, g_xn); GETSYM(QKV, g_qkv); GETSYM(AO, g_ao);
    GETSYM(A1, g_a1); GETSYM(A2, g_a2); GETSYM(A3, g_a3);
    GETSYM(QL, g_ql); GETSYM(KL, g_kl);
    GETSYM(Z0, g_Z0); GETSYM(Z1, g_Z1); GETSYM(T1, g_T1); GETSYM(T2, g_T2); GETSYM(T3, g_T3);
    GETSYM(AV, g_av); GETSYM(W2, g_w2); GETSYM(H, g_h);   GETSYM(HG, g_hg);
    GETSYM(SMAX, g_smax);

    const int DSM = 13056 * 4;  // dynamic smem for depth kernels (52224 B)
    cudaFuncSetAttribute(depth_scores_kernel,  cudaFuncAttributeMaxDynamicSharedMemorySize, DSM);
    cudaFuncSetAttribute(depth_pinv_out_kernel, cudaFuncAttributeMaxDynamicSharedMemorySize, DSM);

    const float SCALE = 0.0721687836487032f; // 192^-0.5

    // ---- patch embed: x = patchify(vol) @ patch_w + patch_b + pos_emb
    {
        long tot = (long)S_TOT * DIMM;
        patchify_kernel<<<(int)((tot + 255) / 256), 256>>>(volume, XN);
        g128(XN, 0, 192, patch_w, 0, 192, 0, X, 0, 192, 1, S_TOT, 192, 192, 1.f,
             patch_b, pos_emb, 0, 192, 1.f);
    }

    for (int i = 0; i < NLAYERS; i++) {
        const float* Wqkv_d = qkv_depth   + (long)i * DIMM * 3 * DIMM;
        const float* Wout_d = outw_depth  + (long)i * DIMM * DIMM;
        const float* bout_d = outb_depth  + (long)i * DIMM;
        const float* Wqkv_s = qkv_spatial + (long)i * DIMM * 3 * DIMM;
        const float* Wout_s = outw_spatial+ (long)i * DIMM * DIMM;
        const float* bout_s = outb_spatial+ (long)i * DIMM;
        const float* W1     = ff_w1 + (long)i * DIMM * 8 * DIMM;
        const float* B1     = ff_b1 + (long)i * 8 * DIMM;
        const float* W2w    = ff_w2 + (long)i * 4 * DIMM * DIMM;
        const float* B2     = ff_b2 + (long)i * DIMM;

        // ================= depth attention (fused) ===========================
        scale_norm_kernel<<<S_TOT / 8, 256>>>(X, XN, gd, i, S_TOT);
        g128(XN, 0, 192, Wqkv_d, 0, 576, 0, QKV, 0, 576, 1, S_TOT, 576, 192, 1.f,
             0, 0, 0, 0, 0.f);
        depth_scores_kernel<<<1024, 256, DSM>>>(QKV, A2);
        zero2_kernel<<<1, 32>>>(SMAX);
        rowabs_max_kernel<<<(1024 * 32 + 7) / 8, 256>>>(A2, SMAX, (long)1024 * 32, 32);
        colabs_max_kernel<<<(1024 * 32 + 255) / 256, 256>>>(A2, SMAX, 1024, 32);
        depth_pinv_out_kernel<<<1024, 256, DSM>>>(A2, QKV, AO, SMAX);
        g128(AO, 0, 192, Wout_d, 0, 192, 0, X, 0, 192, 1, S_TOT, 192, 192, 1.f,
             bout_d, X, 0, 192, 1.f);

        // ================= spatial attention (batch=32, n=1024, m=256) ======
        scale_norm_kernel<<<S_TOT / 8, 256>>>(X, XN, gs, i, S_TOT);
        g128(XN, 0, 192, Wqkv_s, 0, 576, 0, QKV, 0, 576, 1, S_TOT, 576, 192, 1.f,
             0, 0, 0, 0, 0.f);
        landmark_kernel<<<(32 * 256 * 192 + 255) / 256, 256>>>(QKV, QL, KL);
        // a1 = softmax(SCALE * q @ kL^T)  [32,1024,256]
        g128(QKV, (long)1024 * 576, 576, KL, 256 * 192, 192, 1,
             A1, (long)1024 * 256, 256, 32, 1024, 256, 192, SCALE, 0, 0, 0, 0, 0.f);
        // a2 = softmax(SCALE * qL @ kL^T) [32,256,256]
        g128(QL, 256 * 192, 192, KL, 256 * 192, 192, 1,
             A2, 256 * 256, 256, 32, 256, 256, 192, SCALE, 0, 0, 0, 0, 0.f);
        // a3 = softmax(SCALE * qL @ k^T)  [32,256,1024]
        g128(QL, 256 * 192, 192, QKV + 192, (long)1024 * 576, 576, 1,
             A3, (long)256 * 1024, 1024, 32, 256, 1024, 192, SCALE, 0, 0, 0, 0, 0.f);
        softmax_rows(A1, (long)32 * 1024, 256);
        softmax_rows(A2, (long)32 * 256, 256);
        softmax_rows(A3, (long)32 * 256, 1024);
        // pinv(a2), n=256
        zero2_kernel<<<1, 32>>>(SMAX);
        rowabs_max_kernel<<<(32 * 256 + 7) / 8, 256>>>(A2, SMAX, (long)32 * 256, 256);
        colabs_max_kernel<<<(32 * 256 + 255) / 256, 256>>>(A2, SMAX, 32, 256);
        {
            dim3 tg(8, 8, 32);
            transpose_scale_kernel<<<tg, dim3(32, 32)>>>(A2, Z0, SMAX, 256);
        }
        float* Zc = Z0; float* Zn = Z1;
        const long nn = 256 * 256;
        for (int it = 0; it < 6; it++) {
            g128(A2, nn, 256, Zc, nn, 256, 0, T1, nn, 256, 32, 256, 256, 256, 1.f,
                 0, 0, 0, 0, 0.f);
            g128(T1, nn, 256, T1, nn, 256, 0, T2, nn, 256, 32, 256, 256, 256, -1.f,
                 0, T1, nn, 256, 7.f);
            g128(T1, nn, 256, T2, nn, 256, 0, T3, nn, 256, 32, 256, 256, 256, -1.f,
                 0, T1, nn, 256, 15.f);
            g128(Zc, nn, 256, T3, nn, 256, 0, Zn, nn, 256, 32, 256, 256, 256, -0.25f,
                 0, Zc, nn, 256, 3.25f);
            float* t = Zc; Zc = Zn; Zn = t;
        }
        // a3v = a3 @ v  [32,256,192]
        g128(A3, (long)256 * 1024, 1024, QKV + 384, (long)1024 * 576, 576, 0,
             AV, 256 * 192, 192, 32, 256, 192, 1024, 1.f, 0, 0, 0, 0, 0.f);
        // w = Z @ a3v
        g128(Zc, nn, 256, AV, 256 * 192, 192, 0,
             W2, 256 * 192, 192, 32, 256, 192, 256, 1.f, 0, 0, 0, 0, 0.f);
        // out = a1 @ w
        g128(A1, (long)1024 * 256, 256, W2, 256 * 192, 192, 0,
             AO, (long)1024 * 192, 192, 32, 1024, 192, 256, 1.f, 0, 0, 0, 0, 0.f);
        g128(AO, 0, 192, Wout_s, 0, 192, 0, X, 0, 192, 1, S_TOT, 192, 192, 1.f,
             bout_s, X, 0, 192, 1.f);

        // ================= GEGLU feed-forward ================================
        scale_norm_kernel<<<S_TOT / 8, 256>>>(X, XN, gf, i, S_TOT);
        g128(XN, 0, 192, W1, 0, 1536, 0, H, 0, 1536, 1, S_TOT, 1536, 192, 1.f,
             B1, 0, 0, 0, 0.f);
        geglu_kernel<<<(int)(((long)S_TOT * 768 + 255) / 256), 256>>>(H, HG);
        g128(HG, 0, 768, W2w, 0, 192, 0, X, 0, 192, 1, S_TOT, 192, 768, 1.f,
             B2, X, 0, 192, 1.f);
    }

    // ---- final scale norm -> output
    scale_norm_kernel<<<S_TOT / 8, 256>>>(X, (float*)d_out, g_final, 0, S_TOT);
}